// round 16
// baseline (speedup 1.0000x reference)
#include <cuda_runtime.h>
#include <cuda_bf16.h>
#include <math.h>
#include <stdint.h>

// Problem constants
#define BB 256
#define SS 512
#define II 128
#define HH 256
#define J4H 1024          // 4*H gate width

// ---------------------------------------------------------------------------
// Scratch (device globals; no cudaMalloc allowed)
// ---------------------------------------------------------------------------
__device__ float g_G[(size_t)BB * SS * J4H];   // precomputed input gates
__device__ float g_Y1[(size_t)BB * SS * HH];   // layer-1 outputs
__device__ __nv_bfloat16 g_Hh[2][BB * HH];     // hidden hi (bf16), double buf
__device__ __nv_bfloat16 g_Hl[2][BB * HH];     // hidden lo (bf16), double buf

// ---------------------------------------------------------------------------
#define MMA_BF16(CREG, AREG0, AREG1, AREG2, AREG3, BREG0, BREG1)               \
    asm volatile(                                                              \
        "mma.sync.aligned.m16n8k16.row.col.f32.bf16.bf16.f32 "                 \
        "{%0,%1,%2,%3}, {%4,%5,%6,%7}, {%8,%9}, {%0,%1,%2,%3};"                \
        : "+f"(CREG[0]), "+f"(CREG[1]), "+f"(CREG[2]), "+f"(CREG[3])           \
        : "r"(AREG0), "r"(AREG1), "r"(AREG2), "r"(AREG3),                      \
          "r"(BREG0), "r"(BREG1))

#define LDSM_X4(R0, R1, R2, R3, ADDR)                                          \
    asm volatile("ldmatrix.sync.aligned.m8n8.x4.shared.b16 "                   \
                 "{%0,%1,%2,%3}, [%4];"                                        \
                 : "=r"(R0), "=r"(R1), "=r"(R2), "=r"(R3) : "r"(ADDR))

__device__ __forceinline__ uint32_t smem_u32(const void* p) {
    uint32_t a;
    asm("{ .reg .u64 t; cvta.to.shared.u64 t, %1; cvt.u32.u64 %0, t; }"
        : "=r"(a) : "l"(p));
    return a;
}

// ---------------------------------------------------------------------------
// bf16x3 tensor-core GEMM (unchanged — proven at 10.97ms round):
//   C[n,j] = sum_k A[n,k]*W[j,k] + b1[j] + b2[j]     (J fixed = 1024)
// ---------------------------------------------------------------------------
#define AP 36

#define MMA_BF16A(CREG, AREG, BREG)                                            \
    MMA_BF16(CREG, AREG[0], AREG[1], AREG[2], AREG[3], BREG[0], BREG[1])

__global__ __launch_bounds__(256)
void gemm_bias_tc(const float* __restrict__ A,
                  const float* __restrict__ W,
                  const float* __restrict__ b1,
                  const float* __restrict__ b2,
                  float* __restrict__ C,
                  int K)
{
    __shared__ __nv_bfloat16 Ah[128][AP];
    __shared__ __nv_bfloat16 Al[128][AP];
    __shared__ __nv_bfloat16 Wh[64][AP];
    __shared__ __nv_bfloat16 Wl[64][AP];

    const int tid  = threadIdx.x;
    const int lane = tid & 31;
    const int warp = tid >> 5;
    const int wm   = warp & 3;
    const int wn   = warp >> 2;
    const int g    = lane >> 2;
    const int tg   = lane & 3;

    const int j0 = blockIdx.x * 64;
    const int n0 = blockIdx.y * 128;

    float acc[2][4][4];
#pragma unroll
    for (int mt = 0; mt < 2; mt++)
#pragma unroll
        for (int nt = 0; nt < 4; nt++)
#pragma unroll
            for (int i = 0; i < 4; i++) acc[mt][nt][i] = 0.f;

    float bs[4][2];
#pragma unroll
    for (int nt = 0; nt < 4; nt++) {
        int jc = j0 + wn * 32 + nt * 8 + 2 * tg;
        bs[nt][0] = b1[jc] + b2[jc];
        bs[nt][1] = b1[jc + 1] + b2[jc + 1];
    }

    for (int k0 = 0; k0 < K; k0 += 32) {
#pragma unroll
        for (int p = 0; p < 4; p++) {
            int id = tid + p * 256;
            int r  = id >> 3;
            int kc = (id & 7) * 4;
            float4 v = *(const float4*)&A[(size_t)(n0 + r) * K + k0 + kc];
            float vv[4] = {v.x, v.y, v.z, v.w};
#pragma unroll
            for (int i = 0; i < 4; i++) {
                __nv_bfloat16 hi = __float2bfloat16(vv[i]);
                Ah[r][kc + i] = hi;
                Al[r][kc + i] = __float2bfloat16(vv[i] - __bfloat162float(hi));
            }
        }
#pragma unroll
        for (int p = 0; p < 2; p++) {
            int id = tid + p * 256;
            int r  = id >> 3;
            int kc = (id & 7) * 4;
            float4 v = *(const float4*)&W[(size_t)(j0 + r) * K + k0 + kc];
            float vv[4] = {v.x, v.y, v.z, v.w};
#pragma unroll
            for (int i = 0; i < 4; i++) {
                __nv_bfloat16 hi = __float2bfloat16(vv[i]);
                Wh[r][kc + i] = hi;
                Wl[r][kc + i] = __float2bfloat16(vv[i] - __bfloat162float(hi));
            }
        }
        __syncthreads();

#pragma unroll
        for (int ks = 0; ks < 2; ks++) {
            const int c0 = ks * 16 + 2 * tg;

            uint32_t ah[2][4], al[2][4];
#pragma unroll
            for (int mt = 0; mt < 2; mt++) {
                int rb = wm * 32 + mt * 16;
                ah[mt][0] = *(const uint32_t*)&Ah[rb + g][c0];
                ah[mt][1] = *(const uint32_t*)&Ah[rb + g + 8][c0];
                ah[mt][2] = *(const uint32_t*)&Ah[rb + g][c0 + 8];
                ah[mt][3] = *(const uint32_t*)&Ah[rb + g + 8][c0 + 8];
                al[mt][0] = *(const uint32_t*)&Al[rb + g][c0];
                al[mt][1] = *(const uint32_t*)&Al[rb + g + 8][c0];
                al[mt][2] = *(const uint32_t*)&Al[rb + g][c0 + 8];
                al[mt][3] = *(const uint32_t*)&Al[rb + g + 8][c0 + 8];
            }
            uint32_t bh[4][2], bl[4][2];
#pragma unroll
            for (int nt = 0; nt < 4; nt++) {
                int jb = wn * 32 + nt * 8 + g;
                bh[nt][0] = *(const uint32_t*)&Wh[jb][c0];
                bh[nt][1] = *(const uint32_t*)&Wh[jb][c0 + 8];
                bl[nt][0] = *(const uint32_t*)&Wl[jb][c0];
                bl[nt][1] = *(const uint32_t*)&Wl[jb][c0 + 8];
            }

#pragma unroll
            for (int mt = 0; mt < 2; mt++)
#pragma unroll
                for (int nt = 0; nt < 4; nt++) {
                    float* c = acc[mt][nt];
                    MMA_BF16A(c, ah[mt], bh[nt]);
                    MMA_BF16A(c, al[mt], bh[nt]);
                    MMA_BF16A(c, ah[mt], bl[nt]);
                }
        }
        __syncthreads();
    }

#pragma unroll
    for (int mt = 0; mt < 2; mt++) {
#pragma unroll
        for (int nt = 0; nt < 4; nt++) {
            int r0 = n0 + wm * 32 + mt * 16 + g;
            int jc = j0 + wn * 32 + nt * 8 + 2 * tg;
            float2 o0, o1;
            o0.x = acc[mt][nt][0] + bs[nt][0];
            o0.y = acc[mt][nt][1] + bs[nt][1];
            o1.x = acc[mt][nt][2] + bs[nt][0];
            o1.y = acc[mt][nt][3] + bs[nt][1];
            *(float2*)&C[(size_t)r0 * J4H + jc]       = o0;
            *(float2*)&C[(size_t)(r0 + 8) * J4H + jc] = o1;
        }
    }
}

// ---------------------------------------------------------------------------
// Recurrent kernel, 512 threads / 16 warps, ldmatrix fragments.
// Grid = 128 CTAs as 16 clusters of 8. Cluster c: batch [16c,16c+16).
// CTA rank r: h-cols [32r,32r+32) x 4 gates = local n in [0,128).
// Warp (kh = w>>3, nb = w&7): n-band [16nb,16nb+16), k-half kh*128.
// kh=0 -> SmGates, kh=1 -> SmPart; epilogue adds both (no extra sync).
// h exchanged via global bf16 hi/lo (proven R9 path), staged to smem.
// ---------------------------------------------------------------------------
#define WPITCH 264        // bf16 elems per W/H smem row (528B = 33*16B)
#define GP32   136        // fp32 elems per gate smem row
#define SM_WH    0
#define SM_WL    (SM_WH + 128 * WPITCH * 2)          // 67584
#define SM_HHS   (SM_WL + 128 * WPITCH * 2)          // 135168
#define SM_HLS   (SM_HHS + 16 * WPITCH * 2)          // 143616
#define SM_GT    (SM_HLS + 16 * WPITCH * 2)          // 152064
#define SM_PT    (SM_GT + 16 * GP32 * 4)             // 160768
#define LSTM2_SMEM (SM_PT + 16 * GP32 * 4)           // 169472

__device__ __forceinline__ float sigf(float x) {
    return 1.0f / (1.0f + __expf(-x));
}
__device__ __forceinline__ float tanhfast(float x) {
    return 2.0f / (1.0f + __expf(-2.0f * x)) - 1.0f;
}

__global__ __launch_bounds__(512, 1) __cluster_dims__(8, 1, 1)
void lstm_tc_kernel(const float* __restrict__ G,
                    const float* __restrict__ Whh,
                    float* __restrict__ Y,
                    float* __restrict__ hOut,
                    float* __restrict__ cOut)
{
    extern __shared__ char smraw[];
    __nv_bfloat16* WhS = (__nv_bfloat16*)(smraw + SM_WH);
    __nv_bfloat16* WlS = (__nv_bfloat16*)(smraw + SM_WL);
    __nv_bfloat16* HhS = (__nv_bfloat16*)(smraw + SM_HHS);
    __nv_bfloat16* HlS = (__nv_bfloat16*)(smraw + SM_HLS);
    float* SmGates     = (float*)(smraw + SM_GT);    // [16][GP32]
    float* SmPart      = (float*)(smraw + SM_PT);    // [16][GP32]

    const int tid   = threadIdx.x;
    const int lane  = tid & 31;
    const int warp  = tid >> 5;        // 0..15
    const int nb    = warp & 7;        // n-band: [16nb,16nb+16)
    const int kh    = warp >> 3;       // k-half
    const int g     = lane >> 2;
    const int tg    = lane & 3;
    const int rank  = blockIdx.x & 7;
    const int cid   = blockIdx.x >> 3;
    const int b0    = cid * 16;
    const int hbase = rank * 32;
    const int kbase = kh * 128;
    const int n0    = nb * 16;

    // ---- Load + split Whh slice: 128 rows (g4*256 + hbase + jl) x 256 ----
    for (int i = tid; i < 128 * 64; i += 512) {
        int row = i >> 6;              // local n = g4*32 + jl
        int kc  = (i & 63) * 4;
        int g4  = row >> 5;
        int jlw = row & 31;
        float4 v = *(const float4*)
            &Whh[(size_t)(g4 * 256 + hbase + jlw) * 256 + kc];
        float vv[4] = {v.x, v.y, v.z, v.w};
#pragma unroll
        for (int ii = 0; ii < 4; ii++) {
            __nv_bfloat16 hi = __float2bfloat16(vv[ii]);
            WhS[row * WPITCH + kc + ii] = hi;
            WlS[row * WPITCH + kc + ii] =
                __float2bfloat16(vv[ii] - __bfloat162float(hi));
        }
    }
    __syncthreads();

    // ---- ldmatrix lane addresses ----
    // A (16x16 tile): lane -> row (lane&15), col-offset ((lane>>4)*8)
    const uint32_t aRel = ((uint32_t)(lane & 15) * WPITCH +
                           ((lane >> 4) << 3) + kbase) * 2;
    const uint32_t aAddrH = smem_u32(HhS) + aRel;
    const uint32_t aAddrL = smem_u32(HlS) + aRel;
    // B (8 n-rows x 32 k): lane -> n-row (lane&7), k-offset 8*(lane>>3)
    const uint32_t bRel = ((uint32_t)(n0 + (lane & 7)) * WPITCH +
                           ((lane >> 3) << 3) + kbase) * 2;
    const uint32_t bAddrH = smem_u32(WhS) + bRel;
    const uint32_t bAddrL = smem_u32(WlS) + bRel;

    // ---- Epilogue ownership: 1 (b, jl) per thread ----
    const int jl = tid & 31;
    const int bE = tid >> 5;           // 0..15
    const size_t gofs = ((size_t)(b0 + bE) * SS) * J4H + hbase + jl;
    const size_t yofs = ((size_t)(b0 + bE) * SS) * HH + hbase + jl;
    const size_t hofs = (size_t)(b0 + bE) * HH + hbase + jl;
    float cS = 0.f;

    // H staging: thread loads one uint4 (8 bf16) per buffer
    const int stR = tid >> 5;          // row 0..15
    const int stC = (tid & 31) * 8;    // col

    float pre[4];
#pragma unroll
    for (int g4 = 0; g4 < 4; g4++)
        pre[g4] = __ldcg(&G[gofs + g4 * 256]);

    for (int t = 0; t < SS; t++) {
        if (t > 0) {
            // ---- Stage h(t-1): global bf16 hi/lo -> smem ----
            {
                const int rb = (t - 1) & 1;
                const size_t go = (size_t)(b0 + stR) * HH + stC;
                *(uint4*)&HhS[stR * WPITCH + stC] =
                    __ldcg((const uint4*)&g_Hh[rb][go]);
                *(uint4*)&HlS[stR * WPITCH + stC] =
                    __ldcg((const uint4*)&g_Hl[rb][go]);
            }
            __syncthreads();

            // ---- MMA over this warp's k-half, 2 n-tiles ----
            float acc[2][4];
#pragma unroll
            for (int nt = 0; nt < 2; nt++)
#pragma unroll
                for (int i = 0; i < 4; i++) acc[nt][i] = 0.f;

#pragma unroll
            for (int ktp = 0; ktp < 4; ktp++) {
                const uint32_t ko = ktp * 64;   // bytes: 32 k elems
                uint32_t ah0[4], al0[4], ah1[4], al1[4];
                LDSM_X4(ah0[0], ah0[1], ah0[2], ah0[3], aAddrH + ko);
                LDSM_X4(al0[0], al0[1], al0[2], al0[3], aAddrL + ko);
                LDSM_X4(ah1[0], ah1[1], ah1[2], ah1[3], aAddrH + ko + 32);
                LDSM_X4(al1[0], al1[1], al1[2], al1[3], aAddrL + ko + 32);
#pragma unroll
                for (int nt = 0; nt < 2; nt++) {
                    const uint32_t bo = nt * (8 * WPITCH * 2) + ko;
                    uint32_t bh[4], bl[4];
                    LDSM_X4(bh[0], bh[1], bh[2], bh[3], bAddrH + bo);
                    LDSM_X4(bl[0], bl[1], bl[2], bl[3], bAddrL + bo);
                    float* c = acc[nt];
                    MMA_BF16(c, ah0[0], ah0[1], ah0[2], ah0[3], bh[0], bh[1]);
                    MMA_BF16(c, al0[0], al0[1], al0[2], al0[3], bh[0], bh[1]);
                    MMA_BF16(c, ah0[0], ah0[1], ah0[2], ah0[3], bl[0], bl[1]);
                    MMA_BF16(c, ah1[0], ah1[1], ah1[2], ah1[3], bh[2], bh[3]);
                    MMA_BF16(c, al1[0], al1[1], al1[2], al1[3], bh[2], bh[3]);
                    MMA_BF16(c, ah1[0], ah1[1], ah1[2], ah1[3], bl[2], bl[3]);
                }
            }

            // ---- Stage partial gates; kh=0 -> SmGates, kh=1 -> SmPart ----
            float* dst = (kh == 0) ? SmGates : SmPart;
#pragma unroll
            for (int nt = 0; nt < 2; nt++) {
                int col = n0 + 8 * nt + 2 * tg;
                *(float2*)&dst[g * GP32 + col] =
                    make_float2(acc[nt][0], acc[nt][1]);
                *(float2*)&dst[(g + 8) * GP32 + col] =
                    make_float2(acc[nt][2], acc[nt][3]);
            }
            __syncthreads();
        }

        // ---- Epilogue ----
        float gi = pre[0], gf = pre[1], gg = pre[2], go = pre[3];
        if (t > 0) {
            const float* r1 = &SmGates[bE * GP32 + jl];
            const float* r2 = &SmPart[bE * GP32 + jl];
            gi += r1[0]  + r2[0];
            gf += r1[32] + r2[32];
            gg += r1[64] + r2[64];
            go += r1[96] + r2[96];
        }
        float iv = sigf(gi), fv = sigf(gf);
        float gv = tanhfast(gg), ov = sigf(go);
        cS = fv * cS + iv * gv;
        float hv = ov * tanhfast(cS);

        const int wb = t & 1;
        __nv_bfloat16 hi = __float2bfloat16(hv);
        g_Hh[wb][hofs] = hi;
        g_Hl[wb][hofs] = __float2bfloat16(hv - __bfloat162float(hi));
        if (hOut != nullptr && t == SS - 1) {
            hOut[hofs] = hv;
            cOut[hofs] = cS;
        }

        // Release h stores to the cluster.
        asm volatile("barrier.cluster.arrive.aligned;" ::: "memory");

        // Y store + next-step G prefetch overlap the barrier wait.
        Y[yofs + (size_t)t * HH] = hv;
        if (t + 1 < SS) {
#pragma unroll
            for (int g4 = 0; g4 < 4; g4++)
                pre[g4] =
                    __ldcg(&G[gofs + (size_t)(t + 1) * J4H + g4 * 256]);
        }

        asm volatile("barrier.cluster.wait.aligned;" ::: "memory");
    }
}

// ---------------------------------------------------------------------------
// Launch
// ---------------------------------------------------------------------------
extern "C" void kernel_launch(void* const* d_in, const int* in_sizes, int n_in,
                              void* d_out, int out_size)
{
    (void)in_sizes; (void)n_in; (void)out_size;
    const float* x    = (const float*)d_in[0];
    const float* Wih0 = (const float*)d_in[1];
    const float* Whh0 = (const float*)d_in[2];
    const float* bih0 = (const float*)d_in[3];
    const float* bhh0 = (const float*)d_in[4];
    const float* Wih1 = (const float*)d_in[5];
    const float* Whh1 = (const float*)d_in[6];
    const float* bih1 = (const float*)d_in[7];
    const float* bhh1 = (const float*)d_in[8];

    float* y    = (float*)d_out;                        // [B,S,H]
    float* hOut = y + (size_t)BB * SS * HH;             // [1,B,H]
    float* cOut = hOut + (size_t)BB * HH;               // [1,B,H]

    void *pG = nullptr, *pY1 = nullptr;
    cudaGetSymbolAddress(&pG, g_G);
    cudaGetSymbolAddress(&pY1, g_Y1);

    cudaFuncSetAttribute(lstm_tc_kernel,
                         cudaFuncAttributeMaxDynamicSharedMemorySize,
                         LSTM2_SMEM);

    dim3 gemm_grid(J4H / 64, (BB * SS) / 128);

    // Layer 1
    gemm_bias_tc<<<gemm_grid, 256>>>(x, Wih0, bih0, bhh0, (float*)pG, II);
    lstm_tc_kernel<<<128, 512, LSTM2_SMEM>>>(
        (const float*)pG, Whh0, (float*)pY1, nullptr, nullptr);

    // Layer 2
    gemm_bias_tc<<<gemm_grid, 256>>>((const float*)pY1, Wih1, bih1, bhh1,
                                     (float*)pG, HH);
    lstm_tc_kernel<<<128, 512, LSTM2_SMEM>>>(
        (const float*)pG, Whh1, y, hOut, cOut);
}